// round 15
// baseline (speedup 1.0000x reference)
#include <cuda_runtime.h>
#include <cuda_pipeline_primitives.h>
#include <math.h>

#define T_LEN 8192
#define NT    512
#define NV    4                   // float4 chunks per thread
#define EPT   16                  // scalar elements per thread
#define NWARP (NT / 32)           // 16
#define NBIN  2048
#define CMAX  256
#define FULLM 0xffffffffu
#define NSM   152                 // GB300 SM count
#define NSLOT (2 * NSM)           // resident CTA slots (2 CTAs/SM)
#define STAGGER_CYC 8192ll        // ~ one full-BW phase-1 stream window

// ---------------- main kernel: one CTA per batch row ----------------
__global__ __launch_bounds__(NT, 2)
void srp_kernel(const float* __restrict__ g_da,   // dur_anchor_src      [B,T]
                const float* __restrict__ g_lr,   // dur_logratio_unit   [B,T]
                const float* __restrict__ g_pw,   // pause_weight_unit   [B,T]
                const float* __restrict__ g_bl,   // boundary_latent     [B,T]
                const float* __restrict__ g_um,   // unit_mask           [B,T]
                const float* __restrict__ g_sbw,  // speech_budget_win   [B]
                const float* __restrict__ g_pbw,  // pause_budget_win    [B]
                const float* __restrict__ g_pse,  // previous_speech_exec[B,T]
                const float* __restrict__ g_ppe,  // previous_pause_exec [B,T]
                const int*   __restrict__ g_cf,   // commit_frontier     [B]
                float*       __restrict__ g_out,  // [2,B,T]
                int B, int keep_k)
{
    // ---- STAGGER: park (not spin) the wave-1 second partner so its stream
    //      phase lands inside the first partner's serial window.
    if (blockIdx.x >= NSM && blockIdx.x < 2 * NSM) {
        const long long t0 = clock64();
        while (clock64() - t0 < STAGGER_CYC) __nanosleep(256);
    }

    extern __shared__ float smem[];
    float4* sm_um = (float4*)smem;                 // [T/4] um (cp.async staged)
    float4* sm_av = (float4*)(smem + T_LEN);       // [T/4] pw staged -> speech base
    float4* sm_pb = (float4*)(smem + 2 * T_LEN);   // [T/4] bl staged -> pause prefix
    __shared__ int   s_hist[NBIN];
    __shared__ float redf[NWARP][6];
    __shared__ int   s_wcnt[NWARP];
    __shared__ int   s_bin, s_chi, s_m, s_cnt;
    __shared__ float s_comp[CMAX];
    __shared__ float s_thr;

    const int b    = blockIdx.x;
    const int tid  = threadIdx.x;
    const int lane = tid & 31;
    const int warp = tid >> 5;
    const size_t off = (size_t)b * T_LEN;

    const float4* da4  = (const float4*)(g_da  + off);
    const float4* lr4  = (const float4*)(g_lr  + off);
    const float4* pw4  = (const float4*)(g_pw  + off);
    const float4* bl4  = (const float4*)(g_bl  + off);
    const float4* um4  = (const float4*)(g_um  + off);
    const float4* pse4 = (const float4*)(g_pse + off);
    const float4* ppe4 = (const float4*)(g_ppe + off);

    const int   F    = g_cf[b];
    const float sbwv = __ldg(g_sbw + b);
    const float pbwv = __ldg(g_pbw + b);

    float4* out_s4 = (float4*)(g_out + off);
    float4* out_p4 = (float4*)(g_out + (size_t)B * T_LEN + off);

    // ---- stage the 3 unconditional streams via cp.async, ONE COMMIT GROUP
    //      PER CHUNK so compute on chunk j starts after group j only.
    #pragma unroll
    for (int j = 0; j < NV; j++) {
        const int c = tid + j * NT;
        __pipeline_memcpy_async(&sm_um[c], &um4[c], 16);
        __pipeline_memcpy_async(&sm_av[c], &pw4[c], 16);
        __pipeline_memcpy_async(&sm_pb[c], &bl4[c], 16);
        __pipeline_commit();
    }

    // zero histogram while copies fly; ordered before the atomics by B1
    #pragma unroll
    for (int i = 0; i < NBIN / NT; i++) s_hist[tid + i * NT] = 0;

    // ---- phase 1: compute from staged smem + predicated LDGs; reductions;
    //      pure-prefix chunks are fully finished (both planes stored) here.
    float s_r[EPT];
    float a_ps = 0.f, a_pp = 0.f, a_tc = 0.f, a_cs = 0.f, a_mx = 0.f;
    int   a_c0 = 0;
    const float4 zero4 = make_float4(0.f, 0.f, 0.f, 0.f);

    #pragma unroll
    for (int j = 0; j < NV; j++) {
        const int c = tid + j * NT;
        const int ibase = 4 * c;
        const bool has_pref = (ibase < F);            // chunk touches prefix
        const bool has_tail = (ibase + 3 >= F);       // chunk touches tail
        float4 d4 = zero4, l4 = zero4, s4 = zero4, q4 = zero4;
        if (has_tail) { d4 = da4[c];  l4 = lr4[c];  }
        if (has_pref) { s4 = pse4[c]; q4 = ppe4[c]; }
        __pipeline_wait_prior(NV - 1 - j);            // group j landed
        const float4 u4 = sm_um[c];                   // staged
        const float4 p4 = sm_av[c];                   // staged pw
        const float4 b4 = sm_pb[c];                   // staged bl
        float4 av, pb;

#define PROC(E, CMP) {                                                          \
        const float u      = u4.CMP;                                            \
        const float anchor = fmaxf(d4.CMP, 1.0f);                               \
        const float cnd    = fminf(fmaxf(anchor * __expf(l4.CMP), 1.0f),        \
                                   anchor * 3.0f);                              \
        const float sc     = (fmaxf(p4.CMP, 0.f)                                \
                              + 0.15f * (0.1f + fmaxf(b4.CMP, 0.f))) * u;       \
        const bool  pf     = (ibase + E) < F;                                   \
        const float tail   = pf ? 0.f : u;                                      \
        if (pf) { a_ps += s4.CMP * u; a_pp += q4.CMP * u; }                     \
        a_tc += tail;                                                           \
        a_cs += cnd * u * tail;                                                 \
        a_mx  = fmaxf(a_mx, sc);                                                \
        a_c0 += (sc > 0.f);                                                     \
        s_r[4 * j + E] = sc;                                                    \
        av.CMP = pf ? (s4.CMP * u * u) : (cnd * u * u * u);                     \
        pb.CMP = pf ? (q4.CMP * u * u) : 0.f; }

        PROC(0, x) PROC(1, y) PROC(2, z) PROC(3, w)
#undef PROC
        if (!has_tail) {                              // pure-prefix: finish NOW
            out_s4[c] = av;
            out_p4[c] = pb;
        } else {
            sm_av[c] = av;                            // overwrite staged pw
            sm_pb[c] = pb;                            // overwrite staged bl
        }
    }

    // ---- fused 6-way block reduction, ONE barrier, result in all threads ----
    {
        float v0 = a_ps, v1 = a_pp, v2 = a_tc, v3 = a_cs, v4 = a_mx, v5 = (float)a_c0;
        #pragma unroll
        for (int o = 16; o > 0; o >>= 1) {
            v0 += __shfl_xor_sync(FULLM, v0, o);
            v1 += __shfl_xor_sync(FULLM, v1, o);
            v2 += __shfl_xor_sync(FULLM, v2, o);
            v3 += __shfl_xor_sync(FULLM, v3, o);
            v4  = fmaxf(v4, __shfl_xor_sync(FULLM, v4, o));
            v5 += __shfl_xor_sync(FULLM, v5, o);
        }
        if (lane == 0) {
            redf[warp][0] = v0; redf[warp][1] = v1; redf[warp][2] = v2;
            redf[warp][3] = v3; redf[warp][4] = v4; redf[warp][5] = v5;
        }
        __syncthreads();                            // B1 (also orders hist zeroing)
        const bool ok = (lane < NWARP);
        v0 = ok ? redf[lane][0] : 0.f;
        v1 = ok ? redf[lane][1] : 0.f;
        v2 = ok ? redf[lane][2] : 0.f;
        v3 = ok ? redf[lane][3] : 0.f;
        v4 = ok ? redf[lane][4] : 0.f;              // scores >= 0, filler safe for max
        v5 = ok ? redf[lane][5] : 0.f;
        #pragma unroll
        for (int o = 8; o > 0; o >>= 1) {
            v0 += __shfl_xor_sync(FULLM, v0, o);
            v1 += __shfl_xor_sync(FULLM, v1, o);
            v2 += __shfl_xor_sync(FULLM, v2, o);
            v3 += __shfl_xor_sync(FULLM, v3, o);
            v4  = fmaxf(v4, __shfl_xor_sync(FULLM, v4, o));
            v5 += __shfl_xor_sync(FULLM, v5, o);
        }
        a_ps = __shfl_sync(FULLM, v0, 0);
        a_pp = __shfl_sync(FULLM, v1, 0);
        a_tc = __shfl_sync(FULLM, v2, 0);
        a_cs = __shfl_sync(FULLM, v3, 0);
        a_mx = __shfl_sync(FULLM, v4, 0);
        a_c0 = (int)__shfl_sync(FULLM, v5, 0);
    }
    const float ps = a_ps, pp = a_pp, tc = a_tc, cs = a_cs, smx = a_mx;
    const int   c0 = a_c0;

    // ---- per-row scalars ----
    const float sbud    = fmaxf(sbwv, ps + tc);                 // MIN_SPEECH = 1.0
    const float pbud    = fmaxf(pbwv, pp);
    const float rem_s   = sbud - ps;
    const float scale_s = (tc > 0.f && rem_s > 0.f) ? (rem_s / fmaxf(cs, 1e-6f)) : 0.f;
    const float rem_p   = fmaxf(pbud - pp, 0.f);

    // ---- EARLY STORES: speech plane for tail-touching chunks only ----
    #pragma unroll
    for (int j = 0; j < NV; j++) {
        const int c = tid + j * NT;
        const int ibase = 4 * c;
        if (ibase + 3 >= F) {
            const float4 av = sm_av[c];
            float4 os;
            os.x = (ibase + 0 < F) ? av.x : av.x * scale_s;
            os.y = (ibase + 1 < F) ? av.y : av.y * scale_s;
            os.z = (ibase + 2 < F) ? av.z : av.z * scale_s;
            os.w = (ibase + 3 < F) ? av.w : av.w * scale_s;
            out_s4[c] = os;
        }
    }

    // ---- CROSS-WAVE L2 PREFETCH: pull row b+NSLOT's inputs into (shared) L2
    //      during this CTA's selection window. Fire-and-forget, no registers
    //      held, no side effects; wave-2 CTAs then stream from L2 (234 cyc)
    //      instead of DRAM (577 cyc), using bandwidth that idles right now.
    {
        const int b2 = b + NSLOT;
        if (b2 < B) {
            const size_t off2 = (size_t)b2 * T_LEN;
            const int F2 = __ldg(g_cf + b2);
            const int li = tid & 255;                  // 128B line = 32 floats; 256 lines/array
            const size_t eoff = off2 + (size_t)li * 32;
            if (tid < 256) {                           // unconditional streams
                asm volatile("prefetch.global.L2 [%0];" :: "l"(g_um + eoff));
                asm volatile("prefetch.global.L2 [%0];" :: "l"(g_pw + eoff));
                asm volatile("prefetch.global.L2 [%0];" :: "l"(g_bl + eoff));
            } else {                                   // F2-predicated streams
                const int i0 = li * 32;
                if (i0 + 31 >= F2) {
                    asm volatile("prefetch.global.L2 [%0];" :: "l"(g_da + eoff));
                    asm volatile("prefetch.global.L2 [%0];" :: "l"(g_lr + eoff));
                }
                if (i0 < F2) {
                    asm volatile("prefetch.global.L2 [%0];" :: "l"(g_pse + eoff));
                    asm volatile("prefetch.global.L2 [%0];" :: "l"(g_ppe + eoff));
                }
            }
        }
    }

    // ---- exact k-th-largest: hist -> scan -> bin-find -> compact -> finish ----
    float thr = 0.f;
    if (c0 >= keep_k) {                               // uniform branch
        const float hscale = (float)NBIN / smx;       // smx > 0 here

        // 1) histogram (16 spread smem atomics per thread; hist zeroed pre-B1)
        #pragma unroll
        for (int j = 0; j < EPT; j++) {
            int bi = (int)(s_r[j] * hscale);
            bi = (bi > NBIN - 1) ? (NBIN - 1) : bi;
            atomicAdd(&s_hist[bi], 1);
        }
        __syncthreads();                              // B2

        // 2) suffix scan part 1: thread t owns bins 4t..4t+3
        const int h0 = s_hist[4 * tid + 0];
        const int h1 = s_hist[4 * tid + 1];
        const int h2 = s_hist[4 * tid + 2];
        const int h3 = s_hist[4 * tid + 3];
        int sfx = h0 + h1 + h2 + h3;
        #pragma unroll
        for (int o = 1; o < 32; o <<= 1) {
            const int v = __shfl_down_sync(FULLM, sfx, o);
            if (lane + o < 32) sfx += v;
        }
        if (lane == 0) s_wcnt[warp] = sfx;
        if (tid == 0) s_cnt = 0;
        __syncthreads();                              // B3

        // 3) cross-warp suffix + bin find (finder publishes bin, rank base, m)
        {
            int above = 0;
            #pragma unroll
            for (int w = 0; w < NWARP; w++) if (w > warp) above += s_wcnt[w];
            const int S  = above + sfx;
            const int f1 = S - h0;
            const int f2 = f1 - h1;
            const int f3 = f2 - h2;
            const int f4 = f3 - h3;
            if (S  >= keep_k && f1 < keep_k) { s_bin = 4 * tid + 0; s_chi = f1; s_m = h0; }
            if (f1 >= keep_k && f2 < keep_k) { s_bin = 4 * tid + 1; s_chi = f2; s_m = h1; }
            if (f2 >= keep_k && f3 < keep_k) { s_bin = 4 * tid + 2; s_chi = f3; s_m = h2; }
            if (f3 >= keep_k && f4 < keep_k) { s_bin = 4 * tid + 3; s_chi = f4; s_m = h3; }
        }
        __syncthreads();                              // B4
        const int b_sel = s_bin;
        const int kk    = keep_k - s_chi;             // rank within the bin (>=1)
        const int m     = s_m;

        if (m <= CMAX) {
            // 4) atomic-slot compaction (exactly m writers, order irrelevant)
            #pragma unroll
            for (int j = 0; j < EPT; j++) {
                int bi = (int)(s_r[j] * hscale);
                bi = (bi > NBIN - 1) ? (NBIN - 1) : bi;
                if (bi == b_sel) s_comp[atomicAdd(&s_cnt, 1)] = s_r[j];
            }
            __syncthreads();                          // B5

            // 5) warp 0 finishes alone
            if (warp == 0) {
                float thr0;
                if (m <= 32) {
                    const float v = (lane < m) ? s_comp[lane] : -1.f;
                    int r = 0, e = 0;
                    for (int j2 = 0; j2 < m; j2++) {
                        const float vj = __shfl_sync(FULLM, v, j2);
                        r += (vj > v); e += (vj == v);
                    }
                    const bool win = (lane < m) && (r < kk) && (r + e >= kk);
                    const unsigned wm = __ballot_sync(FULLM, win);
                    thr0 = __shfl_sync(FULLM, v, __ffs(wm) - 1);
                } else {
                    // 32 < m <= 256: warp bit-bisection (rare)
                    float cv[8];
                    unsigned mnb = 0x7f7fffffu, mxb = 0u;
                    #pragma unroll
                    for (int t = 0; t < 8; t++) {
                        const int idx = lane + 32 * t;
                        cv[t] = (idx < m) ? s_comp[idx] : -1.f;
                        if (idx < m) {
                            const unsigned bb = __float_as_uint(cv[t]);
                            mnb = (bb < mnb) ? bb : mnb;
                            mxb = (bb > mxb) ? bb : mxb;
                        }
                    }
                    #pragma unroll
                    for (int o = 16; o > 0; o >>= 1) {
                        const unsigned a1 = __shfl_xor_sync(FULLM, mnb, o);
                        const unsigned a2 = __shfl_xor_sync(FULLM, mxb, o);
                        mnb = (a1 < mnb) ? a1 : mnb;
                        mxb = (a2 > mxb) ? a2 : mxb;
                    }
                    unsigned lb = (mnb == 0u) ? 0u : (mnb - 1u), hb = mxb;
                    while (hb - lb > 1u) {
                        const unsigned mb = (lb + hb) >> 1;
                        const float mf = __uint_as_float(mb);
                        int cc = 0;
                        #pragma unroll
                        for (int t = 0; t < 8; t++) cc += (cv[t] > mf);
                        #pragma unroll
                        for (int o = 16; o > 0; o >>= 1) cc += __shfl_xor_sync(FULLM, cc, o);
                        if (cc >= kk) lb = mb; else hb = mb;
                    }
                    thr0 = __uint_as_float(hb);
                }
                if (lane == 0) s_thr = thr0;
            }
            __syncthreads();                          // B6
            thr = s_thr;
        } else {
            // pathological overflow: exact block bit-bisection fallback
            unsigned lo_b = 0u, hi_b = __float_as_uint(smx);
            while (hi_b - lo_b > 1u) {
                const unsigned mid = (lo_b + hi_b) >> 1;
                const float mf = __uint_as_float(mid);
                int cnt = 0;
                #pragma unroll
                for (int j = 0; j < EPT; j++) cnt += (s_r[j] > mf);
                #pragma unroll
                for (int o = 16; o > 0; o >>= 1) cnt += __shfl_xor_sync(FULLM, cnt, o);
                if (lane == 0) s_wcnt[warp] = cnt;
                __syncthreads();
                int tot = 0;
                #pragma unroll
                for (int w = 0; w < NWARP; w++) tot += s_wcnt[w];
                __syncthreads();
                if (tot >= keep_k) lo_b = mid; else hi_b = mid;
            }
            thr = __uint_as_float(hi_b);
        }
    }

    // ---- pause denominator; s_r becomes tcnd*u^2 for tail elems ----
    const float inv_mts = 1e-6f / fmaxf(tc, 1.0f);
    const float itemp   = 1.0f / 0.12f;
    float a_dn = 0.f;
    #pragma unroll
    for (int j = 0; j < NV; j++) {
        const int c = tid + j * NT;
        const int ibase = 4 * c;
        if (ibase + 3 >= F) {                         // chunk has tail elems
            const float4 u4 = sm_um[c];
#define PROCD(E, CMP) {                                                         \
            if ((ibase + E) >= F) {                                             \
                const float u = u4.CMP;                                         \
                const float s = s_r[4 * j + E];                                 \
                const float g = 1.0f / (1.0f + __expf((thr - s) * itemp));      \
                const float tcnd = fmaxf(s * g * u, 0.f) * u + u * inv_mts;     \
                a_dn += tcnd * u;                                               \
                s_r[4 * j + E] = tcnd * u * u;                                  \
            } }
            PROCD(0, x) PROCD(1, y) PROCD(2, z) PROCD(3, w)
#undef PROCD
        }
    }
    {   // single-barrier reduction, all threads get total
        #pragma unroll
        for (int o = 16; o > 0; o >>= 1) a_dn += __shfl_xor_sync(FULLM, a_dn, o);
        if (lane == 0) redf[warp][0] = a_dn;
        __syncthreads();                              // B7 (last barrier)
        float v = (lane < NWARP) ? redf[lane][0] : 0.f;
        #pragma unroll
        for (int o = 8; o > 0; o >>= 1) v += __shfl_xor_sync(FULLM, v, o);
        a_dn = __shfl_sync(FULLM, v, 0);
    }
    const float dn = fmaxf(a_dn, 1e-6f);
    const float scale_p = (tc > 0.f && rem_p > 0.f) ? (rem_p / dn) : 0.f;

    // ---- pause epilogue: only chunks containing tail elems ----
    #pragma unroll
    for (int j = 0; j < NV; j++) {
        const int c = tid + j * NT;
        const int ibase = 4 * c;
        if (ibase + 3 >= F) {
            float4 op;
            if (ibase >= F) {                          // pure tail chunk
                op.x = s_r[4 * j + 0] * scale_p;
                op.y = s_r[4 * j + 1] * scale_p;
                op.z = s_r[4 * j + 2] * scale_p;
                op.w = s_r[4 * j + 3] * scale_p;
            } else {                                   // mixed chunk (<=1 per row)
                const float4 pb = sm_pb[c];
#define PROCP(E, CMP) op.CMP = ((ibase + E) < F) ? pb.CMP                       \
                                                 : (s_r[4 * j + E] * scale_p);
                PROCP(0, x) PROCP(1, y) PROCP(2, z) PROCP(3, w)
#undef PROCP
            }
            out_p4[c] = op;
        }
    }
}

// ---------------- launch ----------------
extern "C" void kernel_launch(void* const* d_in, const int* in_sizes, int n_in,
                              void* d_out, int out_size)
{
    const float* da  = (const float*)d_in[0];
    const float* lr  = (const float*)d_in[1];
    const float* pw  = (const float*)d_in[2];
    const float* bl  = (const float*)d_in[3];
    const float* um  = (const float*)d_in[4];
    const float* sbw = (const float*)d_in[5];
    const float* pbw = (const float*)d_in[6];
    const float* pse = (const float*)d_in[7];
    const float* ppe = (const float*)d_in[8];
    const int*   cf  = (const int*)  d_in[9];
    float* out = (float*)d_out;

    const int B = in_sizes[5];                       // speech_budget_win is [B]
    int keep_k = (int)(0.35 * (double)T_LEN + 0.5);  // round(T*0.35) = 2867
    if (keep_k < 1) keep_k = 1;

    const int smem_bytes = 3 * T_LEN * (int)sizeof(float);   // 96 KB dynamic
    cudaFuncSetAttribute(srp_kernel, cudaFuncAttributeMaxDynamicSharedMemorySize, smem_bytes);

    srp_kernel<<<B, NT, smem_bytes>>>(da, lr, pw, bl, um, sbw, pbw, pse, ppe, cf,
                                      out, B, keep_k);
}